// round 10
// baseline (speedup 1.0000x reference)
#include <cuda_runtime.h>
#include <cuda_bf16.h>

typedef unsigned long long u64;

// Problem constants
#define NRAYS   8192
#define KSEL    4096
#define KSPLIT  64
#define CHUNK   (KSEL / KSPLIT)        // 64 gaussians per block
#define TPB     128
#define NPT     4                      // rays per thread = 2 f32x2 pairs
#define NPAIR   (NPT / 2)
#define RPB     (TPB * NPT)            // 512 rays per block column
#define NBLK    (NRAYS / RPB)          // 16 columns -> grid (16,64) = 1024 blocks

// s = sqrt(0.5 * log2(e)) : folds exp(-0.5 q) -> 2^(-||W d||^2)
#define SCALE_S 0.8493281132464818f
#define FIXSCALE 1073741824.0          // 2^30 fixed-point scale
#define INVFIX   (1.0f / 1073741824.0f)

// ---- scratch (__device__ globals; zero-initialized, self-resetting) -------
__device__ u64      g_acc[NRAYS];     // fixed-point logit accumulators
__device__ unsigned g_cnt[NBLK];      // per-column completion tickets

// ---- packed f32x2 helpers -------------------------------------------------
#define FMA2(d, a, b, c) \
    asm("fma.rn.f32x2 %0, %1, %2, %3;" : "=l"(d) : "l"(a), "l"(b), "l"(c))
#define MUL2(d, a, b) \
    asm("mul.rn.f32x2 %0, %1, %2;" : "=l"(d) : "l"(a), "l"(b))

__device__ __forceinline__ u64 pack2(float lo, float hi) {
    u64 r;
    asm("mov.b64 %0, {%1, %2};" : "=l"(r) : "r"(__float_as_uint(lo)), "r"(__float_as_uint(hi)));
    return r;
}
__device__ __forceinline__ void unpack2(u64 v, float& lo, float& hi) {
    unsigned a, b;
    asm("mov.b64 {%0, %1}, %2;" : "=r"(a), "=r"(b) : "l"(v));
    lo = __uint_as_float(a); hi = __uint_as_float(b);
}
__device__ __forceinline__ u64 dup2(float x) {
    u64 r;
    asm("mov.b64 %0, {%1, %1};" : "=l"(r) : "r"(__float_as_uint(x)));
    return r;
}
__device__ __forceinline__ float ex2f(float x) {
    float e;
    asm("ex2.approx.ftz.f32 %0, %1;" : "=f"(e) : "f"(x));
    return e;
}

// ---------------------------------------------------------------------------
// Single fused kernel: grid (NBLK, KSPLIT), 128 threads.
//  Phase 1 (threads 0..63): gather gaussian, W = s*L^{-1}, nc = -(W*mu),
//    store DUPLICATED f32x2 coefficients (16 u64 per k) in shared.
//  Phase 2: FFMA2 mainloop, 2 ray-pairs per thread over 64 gaussians.
//  Phase 3: deterministic fixed-point integer atomic combine; last block
//    of each ray column applies sigmoid, writes out, resets state.
// ---------------------------------------------------------------------------
__global__ void __launch_bounds__(TPB)
fused_kernel(const float* __restrict__ org,
             const float* __restrict__ dir,
             const float* __restrict__ emb,
             const float* __restrict__ chol,
             const float* __restrict__ labels,
             const int*   __restrict__ idx,
             float* __restrict__ out)
{
    __shared__ u64 smc[CHUNK * 16];    // 8 KB: dup'd coefficients
    __shared__ int s_last;

    const int tid   = threadIdx.x;
    const int nbase = blockIdx.x * RPB;
    const int kbase = blockIdx.y * CHUNK;

    // ---- Phase 1: per-gaussian setup (threads 0..63) ----
    if (tid < CHUNK) {
        int m = __ldg(idx + kbase + tid);
        const float4* c4 = reinterpret_cast<const float4*>(chol) + (size_t)m * 4;
        float4 r0 = c4[0], r1 = c4[1], r2 = c4[2], r3 = c4[3];
        float L00 = r0.x;
        float L10 = r1.x, L11 = r1.y;
        float L20 = r2.x, L21 = r2.y, L22 = r2.z;
        float L30 = r3.x, L31 = r3.y, L32 = r3.z, L33 = r3.w;

        float i0 = 1.0f / L00, i1 = 1.0f / L11, i2 = 1.0f / L22, i3 = 1.0f / L33;

        float U00 = i0, U11 = i1, U22 = i2, U33 = i3;
        float U10 = -(L10 * U00) * i1;
        float U20 = -(L20 * U00 + L21 * U10) * i2;
        float U21 = -(L21 * U11) * i2;
        float U30 = -(L30 * U00 + L31 * U10 + L32 * U20) * i3;
        float U31 = -(L31 * U11 + L32 * U21) * i3;
        float U32 = -(L32 * U22) * i3;

        const float s = SCALE_S;
        U00 *= s; U10 *= s; U11 *= s; U20 *= s; U21 *= s; U22 *= s;
        U30 *= s; U31 *= s; U32 *= s; U33 *= s;

        float4 mu = reinterpret_cast<const float4*>(emb)[m];
        float nc0 = -(U00 * mu.x);
        float nc1 = -(U10 * mu.x + U11 * mu.y);
        float nc2 = -(U20 * mu.x + U21 * mu.y + U22 * mu.z);
        float nc3 = -(U30 * mu.x + U31 * mu.y + U32 * mu.z + U33 * mu.w);
        float lab = __ldg(labels + m);

        u64* o = smc + tid * 16;
        o[0]  = dup2(U00); o[1]  = dup2(U10); o[2]  = dup2(U11); o[3]  = dup2(U20);
        o[4]  = dup2(U21); o[5]  = dup2(U22); o[6]  = dup2(U30); o[7]  = dup2(U31);
        o[8]  = dup2(U32); o[9]  = dup2(U33); o[10] = dup2(nc0); o[11] = dup2(nc1);
        o[12] = dup2(nc2); o[13] = dup2(nc3); o[14] = dup2(lab); o[15] = 0ull;
    }

    // ---- load rays, pack into f32x2 pairs ----
    u64 P0[NPAIR], P1[NPAIR], P2[NPAIR], P3[NPAIR], ACC[NPAIR];
    const float2* o2 = reinterpret_cast<const float2*>(org);
    const float2* d2 = reinterpret_cast<const float2*>(dir);
#pragma unroll
    for (int j = 0; j < NPAIR; j++) {
        int na = nbase + tid + (2 * j) * TPB;
        int nb = nbase + tid + (2 * j + 1) * TPB;
        float2 oa = o2[na], ob = o2[nb];
        float2 da = d2[na], db = d2[nb];
        P0[j] = pack2(oa.x, ob.x);
        P1[j] = pack2(oa.y, ob.y);
        P2[j] = pack2(da.x, db.x);
        P3[j] = pack2(da.y, db.y);
        ACC[j] = 0ull;
    }
    __syncthreads();

    // ---- Phase 2: FFMA2 mainloop ----
#pragma unroll 4
    for (int kk = 0; kk < CHUNK; kk++) {
        const ulonglong2* cp = reinterpret_cast<const ulonglong2*>(smc + kk * 16);
        ulonglong2 a0 = cp[0], a1 = cp[1], a2 = cp[2], a3 = cp[3];
        ulonglong2 a4 = cp[4], a5 = cp[5], a6 = cp[6], a7 = cp[7];
        u64 W00 = a0.x, W10 = a0.y, W11 = a1.x, W20 = a1.y;
        u64 W21 = a2.x, W22 = a2.y, W30 = a3.x, W31 = a3.y;
        u64 W32 = a4.x, W33 = a4.y, NC0 = a5.x, NC1 = a5.y;
        u64 NC2 = a6.x, NC3 = a6.y, LAB = a7.x;

#pragma unroll
        for (int j = 0; j < NPAIR; j++) {
            u64 y0, y1, y2, y3, q;
            FMA2(y0, W00, P0[j], NC0);
            FMA2(y1, W10, P0[j], NC1);
            FMA2(y1, W11, P1[j], y1);
            FMA2(y2, W20, P0[j], NC2);
            FMA2(y2, W21, P1[j], y2);
            FMA2(y2, W22, P2[j], y2);
            FMA2(y3, W30, P0[j], NC3);
            FMA2(y3, W31, P1[j], y3);
            FMA2(y3, W32, P2[j], y3);
            FMA2(y3, W33, P3[j], y3);
            MUL2(q, y0, y0);
            FMA2(q, y1, y1, q);
            FMA2(q, y2, y2, q);
            FMA2(q, y3, y3, q);
            float ql, qh;
            unpack2(q, ql, qh);
            float el = ex2f(-ql);
            float eh = ex2f(-qh);
            u64 e2 = pack2(el, eh);
            FMA2(ACC[j], LAB, e2, ACC[j]);
        }
    }

    // ---- Phase 3: deterministic integer combine ----
#pragma unroll
    for (int j = 0; j < NPAIR; j++) {
        float al, ah;
        unpack2(ACC[j], al, ah);
        int na = nbase + tid + (2 * j) * TPB;
        int nb = nbase + tid + (2 * j + 1) * TPB;
        atomicAdd(&g_acc[na], (u64)(long long)((double)al * FIXSCALE));
        atomicAdd(&g_acc[nb], (u64)(long long)((double)ah * FIXSCALE));
    }
    __threadfence();
    __syncthreads();

    if (tid == 0) {
        unsigned old = atomicAdd(&g_cnt[blockIdx.x], 1u);
        s_last = (old == KSPLIT - 1) ? 1 : 0;
    }
    __syncthreads();

    if (s_last) {
        __threadfence();   // acquire: see all columns' g_acc updates
#pragma unroll
        for (int j = 0; j < NPT; j++) {
            int n = nbase + tid + j * TPB;
            long long v = (long long)__ldcg(&g_acc[n]);
            float s = (float)v * INVFIX;
            float e = ex2f(-s * 1.4426950408889634f);
            out[n] = 1.0f / (1.0f + e);
            g_acc[n] = 0ull;            // reset for next graph replay
        }
        if (tid == 0) g_cnt[blockIdx.x] = 0u;
    }
}

// ---------------------------------------------------------------------------
extern "C" void kernel_launch(void* const* d_in, const int* in_sizes, int n_in,
                              void* d_out, int out_size)
{
    const float* origins    = (const float*)d_in[0];
    const float* directions = (const float*)d_in[1];
    const float* embeddings = (const float*)d_in[2];
    const float* chol       = (const float*)d_in[3];
    const float* labels     = (const float*)d_in[4];
    const int*   idx        = (const int*)  d_in[5];
    float* out = (float*)d_out;

    fused_kernel<<<dim3(NBLK, KSPLIT), TPB>>>(origins, directions, embeddings,
                                              chol, labels, idx, out);
}